// round 9
// baseline (speedup 1.0000x reference)
#include <cuda_runtime.h>
#include <cuda_fp16.h>
#include <math.h>
#include <stdint.h>

// ---------------- problem constants ----------------
#define D_MODEL 1024
#define SEQ     2048
#define BATCH   8
#define CHUNK   16
#define NCHUNKS (SEQ / CHUNK)          // 128
#define ROWS    (SEQ * BATCH)          // 16384
#define STEP_ROWS (NCHUNKS * BATCH)    // 1024 rows per timestep

// ---------------- device scratch (no allocs allowed) ----------------
__device__ float  g_XA [ROWS * D_MODEL];        // x @ A^T           (P-layout, fp32)
__device__ float  g_SEL[ROWS * D_MODEL];        // sigmoid(xW+b)     (P-layout, fp32)
__device__ __half g_H  [ROWS * D_MODEL];        // hidden states     (P-layout, fp16)
__device__ float  g_Y  [ROWS * D_MODEL];        // H @ C^T           (P-layout, fp32)
__device__ __half g_Xh [ROWS * D_MODEL];        // fp16 copy of x    (g-layout)
__device__ __half g_Ah [D_MODEL * D_MODEL];
__device__ __half g_Bh [D_MODEL * D_MODEL];
__device__ __half g_Ch [D_MODEL * D_MODEL];
__device__ __half g_Wh [D_MODEL * D_MODEL];
__device__ unsigned g_bar;                      // grid-barrier ticket counter

// P-layout: row p = t*1024 + chunk*8 + b  for original row g = (chunk*16+t)*8+b
__device__ __forceinline__ int perm_row(int g) {
    int t = (g >> 3) & 15;
    int c = g >> 7;
    int b = g & 7;
    return t * STEP_ROWS + c * 8 + b;
}

__device__ __forceinline__ float sigm(float v) { return 1.0f / (1.0f + __expf(-v)); }

__device__ __forceinline__ uint32_t smem_u32(const void* p) {
    uint32_t a;
    asm("{ .reg .u64 t; cvta.to.shared.u64 t, %1; cvt.u32.u64 %0, t; }" : "=r"(a) : "l"(p));
    return a;
}

__device__ __forceinline__ uint32_t swz(uint32_t o) { return o ^ ((o >> 3) & 0x70); }

__device__ __forceinline__ void ldm_x4(uint32_t* r, uint32_t addr) {
    asm volatile("ldmatrix.sync.aligned.m8n8.x4.shared.b16 {%0,%1,%2,%3}, [%4];"
                 : "=r"(r[0]), "=r"(r[1]), "=r"(r[2]), "=r"(r[3]) : "r"(addr));
}

__device__ __forceinline__ void mma16816(float* c, const uint32_t* a, const uint32_t* b) {
    asm volatile(
        "mma.sync.aligned.m16n8k16.row.col.f32.f16.f16.f32 "
        "{%0,%1,%2,%3}, {%4,%5,%6,%7}, {%8,%9}, {%0,%1,%2,%3};"
        : "+f"(c[0]), "+f"(c[1]), "+f"(c[2]), "+f"(c[3])
        : "r"(a[0]), "r"(a[1]), "r"(a[2]), "r"(a[3]), "r"(b[0]), "r"(b[1]));
}

// Ticket grid barrier: replay-safe (counter only increases). Exactly GRID=128
// increments per instance; instances cleanly separated.
__device__ __forceinline__ void grid_bar() {
    __threadfence();
    __syncthreads();
    if (threadIdx.x == 0) {
        unsigned old = atomicAdd(&g_bar, 1u);
        unsigned target = (old & ~127u) + 128u;
        unsigned cur;
        do {
            asm volatile("ld.volatile.global.u32 %0, [%1];" : "=r"(cur) : "l"(&g_bar));
        } while (cur < target);
    }
    __syncthreads();
}

// ---------------- shared GEMM building blocks ----------------
enum { EPI_NONE = 0, EPI_PERM = 1, EPI_SIG_BIAS_PERM = 2 };

#define STAGES 3
#define B_TILE_BYTES 16384

template <int BM>
__device__ __forceinline__ void load_tile(
    uint32_t sb, int s, const __half* __restrict__ Aop, const __half* __restrict__ Bop,
    int m0, int n0, int kt, int tid)
{
    constexpr int A_TILE_BYTES = BM * 128;
    #pragma unroll
    for (int r = 0; r < (BM * 8) / 256; ++r) {
        int i   = tid + r * 256;
        int row = i >> 3;
        int cc  = i & 7;
        uint32_t sw = swz(row * 128 + cc * 16);
        const __half* ga = Aop + (size_t)(m0 + row) * D_MODEL + kt * 64 + cc * 8;
        asm volatile("cp.async.cg.shared.global [%0], [%1], 16;"
                     :: "r"(sb + s * A_TILE_BYTES + sw), "l"(ga));
    }
    #pragma unroll
    for (int r = 0; r < 4; ++r) {
        int i   = tid + r * 256;
        int row = i >> 3;
        int cc  = i & 7;
        uint32_t sw = swz(row * 128 + cc * 16);
        const __half* gb = Bop + (size_t)(n0 + row) * D_MODEL + kt * 64 + cc * 8;
        asm volatile("cp.async.cg.shared.global [%0], [%1], 16;"
                     :: "r"(sb + STAGES * A_TILE_BYTES + s * B_TILE_BYTES + sw), "l"(gb));
    }
    asm volatile("cp.async.commit_group;" ::: "memory");
}

// 3-stage smem pipeline, single-buffered register fragments.
// acc layout: acc[MT][8][4].
template <int BM, int MT>
__device__ __forceinline__ void gemm_mainloop(
    uint32_t sb, const __half* __restrict__ Aop, const __half* __restrict__ Bop,
    int m0, int n0, int tid, float (*acc)[8][4])
{
    constexpr int A_TILE_BYTES = BM * 128;
    const int wid = tid >> 5, lid = tid & 31;
    const int warp_m = wid & 3;
    const int warp_n = wid >> 2;

    const int a_row = warp_m * (BM / 4) + (lid & 15);
    const int a_kb  = (lid >> 4) * 16;
    const int b_g   = lid >> 3;
    const int b_row = warp_n * 64 + ((b_g >= 2) ? 8 : 0) + (lid & 7);
    const int b_kb  = (b_g & 1) * 16;

    load_tile<BM>(sb, 0, Aop, Bop, m0, n0, 0, tid);
    load_tile<BM>(sb, 1, Aop, Bop, m0, n0, 1, tid);

    #pragma unroll 1
    for (int kt = 0; kt < 16; ++kt) {
        const int s = kt % STAGES;
        asm volatile("cp.async.wait_group 1;" ::: "memory");
        __syncthreads();
        // refill slot (kt+2)%3 (== slot (kt-1)%3, fully consumed last iter)
        if (kt + 2 < 16)
            load_tile<BM>(sb, (kt + 2) % STAGES, Aop, Bop, m0, n0, kt + 2, tid);
        else
            asm volatile("cp.async.commit_group;" ::: "memory");

        const uint32_t sA = sb + s * A_TILE_BYTES;
        const uint32_t sB = sb + STAGES * A_TILE_BYTES + s * B_TILE_BYTES;

        #pragma unroll
        for (int ks = 0; ks < 4; ++ks) {
            uint32_t af[MT][4];
            #pragma unroll
            for (int mt = 0; mt < MT; ++mt)
                ldm_x4(af[mt], sA + swz((a_row + mt * 16) * 128 + ks * 32 + a_kb));
            uint32_t bf[8][2];
            #pragma unroll
            for (int jp = 0; jp < 4; ++jp) {
                uint32_t t4[4];
                ldm_x4(t4, sB + swz((b_row + jp * 16) * 128 + ks * 32 + b_kb));
                bf[2 * jp + 0][0] = t4[0]; bf[2 * jp + 0][1] = t4[1];
                bf[2 * jp + 1][0] = t4[2]; bf[2 * jp + 1][1] = t4[3];
            }
            #pragma unroll
            for (int mt = 0; mt < MT; ++mt)
                #pragma unroll
                for (int nt = 0; nt < 8; ++nt)
                    mma16816(acc[mt][nt], af[mt], bf[nt]);
        }
    }
    __syncthreads();  // all warps done with smem before caller reuses it
}

// ---------------- big GEMM kernel (BM=256, BN=128) ----------------
// 256 threads = 8 warps 4(m)x2(n); warp tile 64x64; acc = 128 regs/thread.
template <int MODE>
__global__ void __launch_bounds__(256) tc_gemm(
    const __half* __restrict__ Aop,
    const __half* __restrict__ Bop,
    float*        __restrict__ out_f,
    const float*  __restrict__ bias)
{
    extern __shared__ __align__(1024) char smem[];
    const uint32_t sb = smem_u32(smem);
    const int tid = threadIdx.x, wid = tid >> 5, lid = tid & 31;
    const int m0 = blockIdx.y * 256, n0 = blockIdx.x * 128;
    const int warp_m = wid & 3, warp_n = wid >> 2;

    float acc[4][8][4];
    #pragma unroll
    for (int mt = 0; mt < 4; ++mt)
        #pragma unroll
        for (int nt = 0; nt < 8; ++nt)
            #pragma unroll
            for (int e = 0; e < 4; ++e) acc[mt][nt][e] = 0.0f;

    gemm_mainloop<256, 4>(sb, Aop, Bop, m0, n0, tid, acc);

    const int er0 = warp_m * 64 + (lid >> 2);
    const int ec  = warp_n * 64 + (lid & 3) * 2;

    #pragma unroll
    for (int mt = 0; mt < 4; ++mt) {
        #pragma unroll
        for (int half = 0; half < 2; ++half) {
            const int row = m0 + er0 + mt * 16 + half * 8;
            int orow = row;
            if constexpr (MODE == EPI_PERM || MODE == EPI_SIG_BIAS_PERM)
                orow = perm_row(row);
            #pragma unroll
            for (int nt = 0; nt < 8; ++nt) {
                const int col = n0 + ec + nt * 8;
                float v0 = acc[mt][nt][2 * half + 0];
                float v1 = acc[mt][nt][2 * half + 1];
                if constexpr (MODE == EPI_SIG_BIAS_PERM) {
                    const float2 bb = *(const float2*)(bias + col);
                    v0 = sigm(v0 + bb.x);
                    v1 = sigm(v1 + bb.y);
                }
                *(float2*)(out_f + (size_t)orow * D_MODEL + col) = make_float2(v0, v1);
            }
        }
    }
}

#define SMEM_BIG  (STAGES * (256 * 128 + B_TILE_BYTES))   // 147456
#define SMEM_STEP (STAGES * (64 * 128 + B_TILE_BYTES))    // 73728

// ---------------- persistent recurrence kernel ----------------
__global__ void __launch_bounds__(256) rec_kernel(
    const __half* __restrict__ Bop,
    __half*       __restrict__ H,
    const float*  __restrict__ XA,
    const float*  __restrict__ SEL)
{
    extern __shared__ __align__(1024) char smem[];
    const uint32_t sb = smem_u32(smem);
    const int tid = threadIdx.x, wid = tid >> 5, lid = tid & 31;
    const int n0 = (blockIdx.x & 7) * 128;
    const int m0 = (blockIdx.x >> 3) * 64;
    const int warp_m = wid & 3, warp_n = wid >> 2;

    // ---- t = 0: elementwise h0 on this CTA's 64x128 patch ----
    #pragma unroll
    for (int r = 0; r < 8; ++r) {
        int i = tid + r * 256;          // 0..2047 float4s
        int row = m0 + (i >> 5);
        int col = n0 + (i & 31) * 4;
        size_t idx = (size_t)row * D_MODEL + col;
        const float4 xa = *(const float4*)(XA + idx);
        const float4 sv = *(const float4*)(SEL + idx);
        __half h[4];
        h[0] = __float2half(tanhf(xa.x) * sv.x);
        h[1] = __float2half(tanhf(xa.y) * sv.y);
        h[2] = __float2half(tanhf(xa.z) * sv.z);
        h[3] = __float2half(tanhf(xa.w) * sv.w);
        *(uint2*)(H + idx) = *(uint2*)h;
    }
    grid_bar();

    const int er0 = warp_m * 16 + (lid >> 2);
    const int ec  = warp_n * 64 + (lid & 3) * 2;

    #pragma unroll 1
    for (int t = 1; t < CHUNK; ++t) {
        const __half* Aprev = H + (size_t)(t - 1) * STEP_ROWS * D_MODEL;

        float acc[1][8][4];
        #pragma unroll
        for (int nt = 0; nt < 8; ++nt)
            #pragma unroll
            for (int e = 0; e < 4; ++e) acc[0][nt][e] = 0.0f;

        gemm_mainloop<64, 1>(sb, Aprev, Bop, m0, n0, tid, acc);

        // epilogue: h = tanh(acc + xa)*sel -> H[t] (fp16)
        const size_t base = (size_t)t * STEP_ROWS * D_MODEL;
        #pragma unroll
        for (int half = 0; half < 2; ++half) {
            const int row = m0 + er0 + half * 8;
            #pragma unroll
            for (int nt = 0; nt < 8; ++nt) {
                const int col = n0 + ec + nt * 8;
                const size_t idx = base + (size_t)row * D_MODEL + col;
                const float2 av = *(const float2*)(XA + idx);
                const float2 sv = *(const float2*)(SEL + idx);
                __half2 hv;
                hv.x = __float2half(tanhf(acc[0][nt][2 * half + 0] + av.x) * sv.x);
                hv.y = __float2half(tanhf(acc[0][nt][2 * half + 1] + av.y) * sv.y);
                *(__half2*)(H + idx) = hv;
            }
        }
        if (t < CHUNK - 1) grid_bar();
    }
}

// ---------------- fp32 -> fp16 conversion ----------------
__global__ void __launch_bounds__(256) f2h_kernel(const float* __restrict__ s,
                                                  __half* __restrict__ d)
{
    const int i = blockIdx.x * blockDim.x + threadIdx.x;
    const float4 v = ((const float4*)s)[i];
    __half h[4];
    h[0] = __float2half(v.x); h[1] = __float2half(v.y);
    h[2] = __float2half(v.z); h[3] = __float2half(v.w);
    ((uint2*)d)[i] = *(uint2*)h;
}

// Per output row g: y = Y_P[perm(g)] + x[g]*D, then LayerNorm -> out[g]
__global__ void __launch_bounds__(256) ln_kernel(
    const float* __restrict__ Y,
    const float* __restrict__ x,
    const float* __restrict__ Dv,
    const float* __restrict__ gamma,
    const float* __restrict__ beta,
    float* __restrict__ out)
{
    const int g = blockIdx.x;
    const int t = (g >> 3) & 15;
    const int c = g >> 7;
    const int b = g & 7;
    const int prow = t * STEP_ROWS + c * 8 + b;

    const int j = threadIdx.x * 4;
    const float4 yv = *(const float4*)(Y  + (size_t)prow * D_MODEL + j);
    const float4 xv = *(const float4*)(x  + (size_t)g    * D_MODEL + j);
    const float4 dv = *(const float4*)(Dv + j);

    float y0 = yv.x + xv.x * dv.x;
    float y1 = yv.y + xv.y * dv.y;
    float y2 = yv.z + xv.z * dv.z;
    float y3 = yv.w + xv.w * dv.w;

    float s  = y0 + y1 + y2 + y3;
    float ss = y0 * y0 + y1 * y1 + y2 * y2 + y3 * y3;

    #pragma unroll
    for (int off = 16; off; off >>= 1) {
        s  += __shfl_xor_sync(0xffffffffu, s,  off);
        ss += __shfl_xor_sync(0xffffffffu, ss, off);
    }
    __shared__ float sh_s[8], sh_ss[8];
    const int w = threadIdx.x >> 5, l = threadIdx.x & 31;
    if (l == 0) { sh_s[w] = s; sh_ss[w] = ss; }
    __syncthreads();
    if (w == 0) {
        s  = (l < 8) ? sh_s[l]  : 0.0f;
        ss = (l < 8) ? sh_ss[l] : 0.0f;
        #pragma unroll
        for (int off = 4; off; off >>= 1) {
            s  += __shfl_xor_sync(0xffffffffu, s,  off);
            ss += __shfl_xor_sync(0xffffffffu, ss, off);
        }
        if (l == 0) { sh_s[0] = s; sh_ss[0] = ss; }
    }
    __syncthreads();
    const float mean = sh_s[0] * (1.0f / D_MODEL);
    const float var  = sh_ss[0] * (1.0f / D_MODEL) - mean * mean;
    const float inv  = rsqrtf(var + 1e-5f);

    const float4 gm = *(const float4*)(gamma + j);
    const float4 bt = *(const float4*)(beta  + j);
    float4 o;
    o.x = (y0 - mean) * inv * gm.x + bt.x;
    o.y = (y1 - mean) * inv * gm.y + bt.y;
    o.z = (y2 - mean) * inv * gm.z + bt.z;
    o.w = (y3 - mean) * inv * gm.w + bt.w;
    *(float4*)(out + (size_t)g * D_MODEL + j) = o;
}

// ---------------- launch ----------------
extern "C" void kernel_launch(void* const* d_in, const int* in_sizes, int n_in,
                              void* d_out, int out_size)
{
    (void)in_sizes; (void)n_in; (void)out_size;
    const float* x     = (const float*)d_in[0];
    const float* A     = (const float*)d_in[1];
    const float* B     = (const float*)d_in[2];
    const float* C     = (const float*)d_in[3];
    const float* Dv    = (const float*)d_in[4];
    const float* W_sel = (const float*)d_in[5];
    const float* b_sel = (const float*)d_in[6];
    const float* gamma = (const float*)d_in[7];
    const float* beta  = (const float*)d_in[8];
    float* out = (float*)d_out;

    float *XA, *SEL, *Y;
    __half *H, *Xh, *Ah, *Bh, *Ch, *Wh;
    cudaGetSymbolAddress((void**)&XA,  g_XA);
    cudaGetSymbolAddress((void**)&SEL, g_SEL);
    cudaGetSymbolAddress((void**)&H,   g_H);
    cudaGetSymbolAddress((void**)&Y,   g_Y);
    cudaGetSymbolAddress((void**)&Xh,  g_Xh);
    cudaGetSymbolAddress((void**)&Ah,  g_Ah);
    cudaGetSymbolAddress((void**)&Bh,  g_Bh);
    cudaGetSymbolAddress((void**)&Ch,  g_Ch);
    cudaGetSymbolAddress((void**)&Wh,  g_Wh);

    cudaFuncSetAttribute(tc_gemm<EPI_NONE>,          cudaFuncAttributeMaxDynamicSharedMemorySize, SMEM_BIG);
    cudaFuncSetAttribute(tc_gemm<EPI_PERM>,          cudaFuncAttributeMaxDynamicSharedMemorySize, SMEM_BIG);
    cudaFuncSetAttribute(tc_gemm<EPI_SIG_BIAS_PERM>, cudaFuncAttributeMaxDynamicSharedMemorySize, SMEM_BIG);
    cudaFuncSetAttribute(rec_kernel,                 cudaFuncAttributeMaxDynamicSharedMemorySize, SMEM_STEP);

    // fp16 conversions
    f2h_kernel<<<(ROWS * D_MODEL / 4) / 256, 256>>>(x, Xh);
    f2h_kernel<<<(D_MODEL * D_MODEL / 4) / 256, 256>>>(A, Ah);
    f2h_kernel<<<(D_MODEL * D_MODEL / 4) / 256, 256>>>(B, Bh);
    f2h_kernel<<<(D_MODEL * D_MODEL / 4) / 256, 256>>>(C, Ch);
    f2h_kernel<<<(D_MODEL * D_MODEL / 4) / 256, 256>>>(W_sel, Wh);

    const dim3 big_grid(D_MODEL / 128, ROWS / 256);        // 8 x 64

    // SEL = sigmoid(x @ Wsel^T + b)  (P-layout fp32)
    tc_gemm<EPI_SIG_BIAS_PERM><<<big_grid, 256, SMEM_BIG>>>(Xh, Wh, SEL, b_sel);
    // XA = x @ A^T  (P-layout fp32)
    tc_gemm<EPI_PERM><<<big_grid, 256, SMEM_BIG>>>(Xh, Ah, XA, nullptr);
    // full recurrence (h0 + 15 steps) in one persistent kernel
    rec_kernel<<<128, 256, SMEM_STEP>>>(Bh, H, XA, SEL);
    // Y = H @ C^T  (P-layout fp32)
    tc_gemm<EPI_NONE><<<big_grid, 256, SMEM_BIG>>>(H, Ch, Y, nullptr);
    // LayerNorm + x*D + un-permute
    ln_kernel<<<ROWS, 256>>>(Y, x, Dv, gamma, beta, out);
}

// round 11
// speedup vs baseline: 1.1729x; 1.1729x over previous
#include <cuda_runtime.h>
#include <cuda_fp16.h>
#include <math.h>
#include <stdint.h>

// ---------------- problem constants ----------------
#define D_MODEL 1024
#define SEQ     2048
#define BATCH   8
#define CHUNK   16
#define NCHUNKS (SEQ / CHUNK)          // 128
#define ROWS    (SEQ * BATCH)          // 16384
#define STEP_ROWS (NCHUNKS * BATCH)    // 1024 rows per timestep

// ---------------- device scratch (no allocs allowed) ----------------
__device__ float  g_XA [ROWS * D_MODEL];        // x @ A^T           (P-layout, fp32)
__device__ float  g_SEL[ROWS * D_MODEL];        // sigmoid(xW+b)     (P-layout, fp32)
__device__ __half g_H  [ROWS * D_MODEL];        // hidden states     (P-layout, fp16)
__device__ float  g_Y  [ROWS * D_MODEL];        // H @ C^T           (P-layout, fp32)
__device__ __half g_Xh [ROWS * D_MODEL];        // fp16 copy of x    (g-layout)
__device__ __half g_Ah [D_MODEL * D_MODEL];
__device__ __half g_Bh [D_MODEL * D_MODEL];
__device__ __half g_Ch [D_MODEL * D_MODEL];
__device__ __half g_Wh [D_MODEL * D_MODEL];
__device__ unsigned g_bar;                      // grid-barrier ticket counter

// P-layout: row p = t*1024 + chunk*8 + b  for original row g = (chunk*16+t)*8+b
__device__ __forceinline__ int perm_row(int g) {
    int t = (g >> 3) & 15;
    int c = g >> 7;
    int b = g & 7;
    return t * STEP_ROWS + c * 8 + b;
}

__device__ __forceinline__ float sigm(float v) { return 1.0f / (1.0f + __expf(-v)); }

__device__ __forceinline__ uint32_t smem_u32(const void* p) {
    uint32_t a;
    asm("{ .reg .u64 t; cvta.to.shared.u64 t, %1; cvt.u32.u64 %0, t; }" : "=r"(a) : "l"(p));
    return a;
}

__device__ __forceinline__ uint32_t swz(uint32_t o) { return o ^ ((o >> 3) & 0x70); }

__device__ __forceinline__ void ldm_x4(uint32_t* r, uint32_t addr) {
    asm volatile("ldmatrix.sync.aligned.m8n8.x4.shared.b16 {%0,%1,%2,%3}, [%4];"
                 : "=r"(r[0]), "=r"(r[1]), "=r"(r[2]), "=r"(r[3]) : "r"(addr));
}

__device__ __forceinline__ void mma16816(float* c, const uint32_t* a, const uint32_t* b) {
    asm volatile(
        "mma.sync.aligned.m16n8k16.row.col.f32.f16.f16.f32 "
        "{%0,%1,%2,%3}, {%4,%5,%6,%7}, {%8,%9}, {%0,%1,%2,%3};"
        : "+f"(c[0]), "+f"(c[1]), "+f"(c[2]), "+f"(c[3])
        : "r"(a[0]), "r"(a[1]), "r"(a[2]), "r"(a[3]), "r"(b[0]), "r"(b[1]));
}

// Ticket grid barrier: replay-safe (counter only increases). Exactly GRID=128
// increments per instance; instances cleanly separated.
__device__ __forceinline__ void grid_bar() {
    __threadfence();
    __syncthreads();
    if (threadIdx.x == 0) {
        unsigned old = atomicAdd(&g_bar, 1u);
        unsigned target = (old & ~127u) + 128u;
        unsigned cur;
        do {
            asm volatile("ld.volatile.global.u32 %0, [%1];" : "=r"(cur) : "l"(&g_bar));
        } while (cur < target);
    }
    __syncthreads();
}

// ---------------- shared GEMM building blocks ----------------
enum { EPI_NONE = 0, EPI_PERM = 1, EPI_SIG_BIAS_PERM = 2 };

#define STAGES 3
#define B_TILE_BYTES 16384

template <int BM>
__device__ __forceinline__ void load_tile(
    uint32_t sb, int s, const __half* __restrict__ Aop, const __half* __restrict__ Bop,
    int m0, int n0, int kt, int tid)
{
    constexpr int A_TILE_BYTES = BM * 128;
    #pragma unroll
    for (int r = 0; r < (BM * 8) / 256; ++r) {
        int i   = tid + r * 256;
        int row = i >> 3;
        int cc  = i & 7;
        uint32_t sw = swz(row * 128 + cc * 16);
        const __half* ga = Aop + (size_t)(m0 + row) * D_MODEL + kt * 64 + cc * 8;
        asm volatile("cp.async.cg.shared.global [%0], [%1], 16;"
                     :: "r"(sb + s * A_TILE_BYTES + sw), "l"(ga));
    }
    #pragma unroll
    for (int r = 0; r < 4; ++r) {
        int i   = tid + r * 256;
        int row = i >> 3;
        int cc  = i & 7;
        uint32_t sw = swz(row * 128 + cc * 16);
        const __half* gb = Bop + (size_t)(n0 + row) * D_MODEL + kt * 64 + cc * 8;
        asm volatile("cp.async.cg.shared.global [%0], [%1], 16;"
                     :: "r"(sb + STAGES * A_TILE_BYTES + s * B_TILE_BYTES + sw), "l"(gb));
    }
    asm volatile("cp.async.commit_group;" ::: "memory");
}

// 3-stage smem pipeline, single-buffered register fragments.
// acc layout: acc[MT][8][4].
template <int BM, int MT>
__device__ __forceinline__ void gemm_mainloop(
    uint32_t sb, const __half* __restrict__ Aop, const __half* __restrict__ Bop,
    int m0, int n0, int tid, float (*acc)[8][4])
{
    constexpr int A_TILE_BYTES = BM * 128;
    const int wid = tid >> 5, lid = tid & 31;
    const int warp_m = wid & 3;
    const int warp_n = wid >> 2;

    const int a_row = warp_m * (BM / 4) + (lid & 15);
    const int a_kb  = (lid >> 4) * 16;
    const int b_g   = lid >> 3;
    const int b_row = warp_n * 64 + ((b_g >= 2) ? 8 : 0) + (lid & 7);
    const int b_kb  = (b_g & 1) * 16;

    load_tile<BM>(sb, 0, Aop, Bop, m0, n0, 0, tid);
    load_tile<BM>(sb, 1, Aop, Bop, m0, n0, 1, tid);

    #pragma unroll 1
    for (int kt = 0; kt < 16; ++kt) {
        const int s = kt % STAGES;
        asm volatile("cp.async.wait_group 1;" ::: "memory");
        __syncthreads();
        // refill slot (kt+2)%3 (== slot (kt-1)%3, fully consumed last iter)
        if (kt + 2 < 16)
            load_tile<BM>(sb, (kt + 2) % STAGES, Aop, Bop, m0, n0, kt + 2, tid);
        else
            asm volatile("cp.async.commit_group;" ::: "memory");

        const uint32_t sA = sb + s * A_TILE_BYTES;
        const uint32_t sB = sb + STAGES * A_TILE_BYTES + s * B_TILE_BYTES;

        #pragma unroll
        for (int ks = 0; ks < 4; ++ks) {
            uint32_t af[MT][4];
            #pragma unroll
            for (int mt = 0; mt < MT; ++mt)
                ldm_x4(af[mt], sA + swz((a_row + mt * 16) * 128 + ks * 32 + a_kb));
            uint32_t bf[8][2];
            #pragma unroll
            for (int jp = 0; jp < 4; ++jp) {
                uint32_t t4[4];
                ldm_x4(t4, sB + swz((b_row + jp * 16) * 128 + ks * 32 + b_kb));
                bf[2 * jp + 0][0] = t4[0]; bf[2 * jp + 0][1] = t4[1];
                bf[2 * jp + 1][0] = t4[2]; bf[2 * jp + 1][1] = t4[3];
            }
            #pragma unroll
            for (int mt = 0; mt < MT; ++mt)
                #pragma unroll
                for (int nt = 0; nt < 8; ++nt)
                    mma16816(acc[mt][nt], af[mt], bf[nt]);
        }
    }
    __syncthreads();  // all warps done with smem before caller reuses it
}

// ---------------- big GEMM kernel (BM=128, BN=128) ----------------
template <int MODE>
__global__ void __launch_bounds__(256) tc_gemm(
    const __half* __restrict__ Aop,
    const __half* __restrict__ Bop,
    float*        __restrict__ out_f,
    const float*  __restrict__ bias)
{
    extern __shared__ __align__(1024) char smem[];
    const uint32_t sb = smem_u32(smem);
    const int tid = threadIdx.x, wid = tid >> 5, lid = tid & 31;
    const int m0 = blockIdx.y * 128, n0 = blockIdx.x * 128;
    const int warp_m = wid & 3, warp_n = wid >> 2;

    float acc[2][8][4];
    #pragma unroll
    for (int mt = 0; mt < 2; ++mt)
        #pragma unroll
        for (int nt = 0; nt < 8; ++nt)
            #pragma unroll
            for (int e = 0; e < 4; ++e) acc[mt][nt][e] = 0.0f;

    gemm_mainloop<128, 2>(sb, Aop, Bop, m0, n0, tid, acc);

    const int er0 = warp_m * 32 + (lid >> 2);
    const int ec  = warp_n * 64 + (lid & 3) * 2;

    #pragma unroll
    for (int mt = 0; mt < 2; ++mt) {
        #pragma unroll
        for (int half = 0; half < 2; ++half) {
            const int row = m0 + er0 + mt * 16 + half * 8;
            int orow = row;
            if constexpr (MODE == EPI_PERM || MODE == EPI_SIG_BIAS_PERM)
                orow = perm_row(row);
            #pragma unroll
            for (int nt = 0; nt < 8; ++nt) {
                const int col = n0 + ec + nt * 8;
                float v0 = acc[mt][nt][2 * half + 0];
                float v1 = acc[mt][nt][2 * half + 1];
                if constexpr (MODE == EPI_SIG_BIAS_PERM) {
                    const float2 bb = *(const float2*)(bias + col);
                    v0 = sigm(v0 + bb.x);
                    v1 = sigm(v1 + bb.y);
                }
                *(float2*)(out_f + (size_t)orow * D_MODEL + col) = make_float2(v0, v1);
            }
        }
    }
}

#define SMEM_BIG  (STAGES * (128 * 128 + B_TILE_BYTES))   // 98304
#define SMEM_STEP (STAGES * (64 * 128 + B_TILE_BYTES))    // 73728

// ---------------- persistent recurrence kernel ----------------
__global__ void __launch_bounds__(256) rec_kernel(
    const __half* __restrict__ Bop,
    __half*       __restrict__ H,
    const float*  __restrict__ XA,
    const float*  __restrict__ SEL)
{
    extern __shared__ __align__(1024) char smem[];
    const uint32_t sb = smem_u32(smem);
    const int tid = threadIdx.x, wid = tid >> 5, lid = tid & 31;
    const int n0 = (blockIdx.x & 7) * 128;
    const int m0 = (blockIdx.x >> 3) * 64;
    const int warp_m = wid & 3, warp_n = wid >> 2;

    // ---- t = 0: elementwise h0 on this CTA's 64x128 patch ----
    #pragma unroll
    for (int r = 0; r < 8; ++r) {
        int i = tid + r * 256;          // 0..2047 float4s
        int row = m0 + (i >> 5);
        int col = n0 + (i & 31) * 4;
        size_t idx = (size_t)row * D_MODEL + col;
        const float4 xa = *(const float4*)(XA + idx);
        const float4 sv = *(const float4*)(SEL + idx);
        __half h[4];
        h[0] = __float2half(tanhf(xa.x) * sv.x);
        h[1] = __float2half(tanhf(xa.y) * sv.y);
        h[2] = __float2half(tanhf(xa.z) * sv.z);
        h[3] = __float2half(tanhf(xa.w) * sv.w);
        *(uint2*)(H + idx) = *(uint2*)h;
    }
    grid_bar();

    const int er0 = warp_m * 16 + (lid >> 2);
    const int ec  = warp_n * 64 + (lid & 3) * 2;

    #pragma unroll 1
    for (int t = 1; t < CHUNK; ++t) {
        const __half* Aprev = H + (size_t)(t - 1) * STEP_ROWS * D_MODEL;

        float acc[1][8][4];
        #pragma unroll
        for (int nt = 0; nt < 8; ++nt)
            #pragma unroll
            for (int e = 0; e < 4; ++e) acc[0][nt][e] = 0.0f;

        gemm_mainloop<64, 1>(sb, Aprev, Bop, m0, n0, tid, acc);

        // epilogue: h = tanh(acc + xa)*sel -> H[t] (fp16)
        const size_t base = (size_t)t * STEP_ROWS * D_MODEL;
        #pragma unroll
        for (int half = 0; half < 2; ++half) {
            const int row = m0 + er0 + half * 8;
            #pragma unroll
            for (int nt = 0; nt < 8; ++nt) {
                const int col = n0 + ec + nt * 8;
                const size_t idx = base + (size_t)row * D_MODEL + col;
                const float2 av = *(const float2*)(XA + idx);
                const float2 sv = *(const float2*)(SEL + idx);
                __half2 hv;
                hv.x = __float2half(tanhf(acc[0][nt][2 * half + 0] + av.x) * sv.x);
                hv.y = __float2half(tanhf(acc[0][nt][2 * half + 1] + av.y) * sv.y);
                *(__half2*)(H + idx) = hv;
            }
        }
        if (t < CHUNK - 1) grid_bar();
    }
}

// ---------------- fp32 -> fp16 conversions ----------------
__global__ void __launch_bounds__(256) f2h_kernel(const float* __restrict__ s,
                                                  __half* __restrict__ d)
{
    const int i = blockIdx.x * blockDim.x + threadIdx.x;
    const float4 v = ((const float4*)s)[i];
    __half h[4];
    h[0] = __float2half(v.x); h[1] = __float2half(v.y);
    h[2] = __float2half(v.z); h[3] = __float2half(v.w);
    ((uint2*)d)[i] = *(uint2*)h;
}

// all 4 weight matrices in one launch: blockIdx.x>>10 selects the matrix
__global__ void __launch_bounds__(256) f2h_w4_kernel(
    const float* __restrict__ s0, __half* __restrict__ d0,
    const float* __restrict__ s1, __half* __restrict__ d1,
    const float* __restrict__ s2, __half* __restrict__ d2,
    const float* __restrict__ s3, __half* __restrict__ d3)
{
    const int m = blockIdx.x >> 10;                 // 0..3
    const int i = (blockIdx.x & 1023) * blockDim.x + threadIdx.x;
    const float* s = (m == 0) ? s0 : (m == 1) ? s1 : (m == 2) ? s2 : s3;
    __half*      d = (m == 0) ? d0 : (m == 1) ? d1 : (m == 2) ? d2 : d3;
    const float4 v = ((const float4*)s)[i];
    __half h[4];
    h[0] = __float2half(v.x); h[1] = __float2half(v.y);
    h[2] = __float2half(v.z); h[3] = __float2half(v.w);
    ((uint2*)d)[i] = *(uint2*)h;
}

// Per output row g: y = Y_P[perm(g)] + x[g]*D, then LayerNorm -> out[g]
__global__ void __launch_bounds__(256) ln_kernel(
    const float* __restrict__ Y,
    const float* __restrict__ x,
    const float* __restrict__ Dv,
    const float* __restrict__ gamma,
    const float* __restrict__ beta,
    float* __restrict__ out)
{
    const int g = blockIdx.x;
    const int t = (g >> 3) & 15;
    const int c = g >> 7;
    const int b = g & 7;
    const int prow = t * STEP_ROWS + c * 8 + b;

    const int j = threadIdx.x * 4;
    const float4 yv = *(const float4*)(Y  + (size_t)prow * D_MODEL + j);
    const float4 xv = *(const float4*)(x  + (size_t)g    * D_MODEL + j);
    const float4 dv = *(const float4*)(Dv + j);

    float y0 = yv.x + xv.x * dv.x;
    float y1 = yv.y + xv.y * dv.y;
    float y2 = yv.z + xv.z * dv.z;
    float y3 = yv.w + xv.w * dv.w;

    float s  = y0 + y1 + y2 + y3;
    float ss = y0 * y0 + y1 * y1 + y2 * y2 + y3 * y3;

    #pragma unroll
    for (int off = 16; off; off >>= 1) {
        s  += __shfl_xor_sync(0xffffffffu, s,  off);
        ss += __shfl_xor_sync(0xffffffffu, ss, off);
    }
    __shared__ float sh_s[8], sh_ss[8];
    const int w = threadIdx.x >> 5, l = threadIdx.x & 31;
    if (l == 0) { sh_s[w] = s; sh_ss[w] = ss; }
    __syncthreads();
    if (w == 0) {
        s  = (l < 8) ? sh_s[l]  : 0.0f;
        ss = (l < 8) ? sh_ss[l] : 0.0f;
        #pragma unroll
        for (int off = 4; off; off >>= 1) {
            s  += __shfl_xor_sync(0xffffffffu, s,  off);
            ss += __shfl_xor_sync(0xffffffffu, ss, off);
        }
        if (l == 0) { sh_s[0] = s; sh_ss[0] = ss; }
    }
    __syncthreads();
    const float mean = sh_s[0] * (1.0f / D_MODEL);
    const float var  = sh_ss[0] * (1.0f / D_MODEL) - mean * mean;
    const float inv  = rsqrtf(var + 1e-5f);

    const float4 gm = *(const float4*)(gamma + j);
    const float4 bt = *(const float4*)(beta  + j);
    float4 o;
    o.x = (y0 - mean) * inv * gm.x + bt.x;
    o.y = (y1 - mean) * inv * gm.y + bt.y;
    o.z = (y2 - mean) * inv * gm.z + bt.z;
    o.w = (y3 - mean) * inv * gm.w + bt.w;
    *(float4*)(out + (size_t)g * D_MODEL + j) = o;
}

// ---------------- launch ----------------
extern "C" void kernel_launch(void* const* d_in, const int* in_sizes, int n_in,
                              void* d_out, int out_size)
{
    (void)in_sizes; (void)n_in; (void)out_size;
    const float* x     = (const float*)d_in[0];
    const float* A     = (const float*)d_in[1];
    const float* B     = (const float*)d_in[2];
    const float* C     = (const float*)d_in[3];
    const float* Dv    = (const float*)d_in[4];
    const float* W_sel = (const float*)d_in[5];
    const float* b_sel = (const float*)d_in[6];
    const float* gamma = (const float*)d_in[7];
    const float* beta  = (const float*)d_in[8];
    float* out = (float*)d_out;

    float *XA, *SEL, *Y;
    __half *H, *Xh, *Ah, *Bh, *Ch, *Wh;
    cudaGetSymbolAddress((void**)&XA,  g_XA);
    cudaGetSymbolAddress((void**)&SEL, g_SEL);
    cudaGetSymbolAddress((void**)&H,   g_H);
    cudaGetSymbolAddress((void**)&Y,   g_Y);
    cudaGetSymbolAddress((void**)&Xh,  g_Xh);
    cudaGetSymbolAddress((void**)&Ah,  g_Ah);
    cudaGetSymbolAddress((void**)&Bh,  g_Bh);
    cudaGetSymbolAddress((void**)&Ch,  g_Ch);
    cudaGetSymbolAddress((void**)&Wh,  g_Wh);

    cudaFuncSetAttribute(tc_gemm<EPI_NONE>,          cudaFuncAttributeMaxDynamicSharedMemorySize, SMEM_BIG);
    cudaFuncSetAttribute(tc_gemm<EPI_PERM>,          cudaFuncAttributeMaxDynamicSharedMemorySize, SMEM_BIG);
    cudaFuncSetAttribute(tc_gemm<EPI_SIG_BIAS_PERM>, cudaFuncAttributeMaxDynamicSharedMemorySize, SMEM_BIG);
    cudaFuncSetAttribute(rec_kernel,                 cudaFuncAttributeMaxDynamicSharedMemorySize, SMEM_STEP);

    // launch 1: x -> fp16
    f2h_kernel<<<(ROWS * D_MODEL / 4) / 256, 256>>>(x, Xh);
    // launch 2: all 4 weight matrices -> fp16 (one kernel)
    f2h_w4_kernel<<<4096, 256>>>(A, Ah, B, Bh, C, Ch, W_sel, Wh);

    const dim3 big_grid(D_MODEL / 128, ROWS / 128);        // 8 x 128

    // launch 3: SEL = sigmoid(x @ Wsel^T + b)  (P-layout fp32)
    tc_gemm<EPI_SIG_BIAS_PERM><<<big_grid, 256, SMEM_BIG>>>(Xh, Wh, SEL, b_sel);
    // launch 4: XA = x @ A^T  (P-layout fp32)
    tc_gemm<EPI_PERM><<<big_grid, 256, SMEM_BIG>>>(Xh, Ah, XA, nullptr);
    // launch 5: full recurrence (h0 + 15 steps), persistent
    rec_kernel<<<128, 256, SMEM_STEP>>>(Bh, H, XA, SEL);
    // launch 6: Y = H @ C^T  (P-layout fp32)
    tc_gemm<EPI_NONE><<<big_grid, 256, SMEM_BIG>>>(H, Ch, Y, nullptr);
    // launch 7: LayerNorm + x*D + un-permute
    ln_kernel<<<ROWS, 256>>>(Y, x, Dv, gamma, beta, out);
}

// round 12
// speedup vs baseline: 1.1901x; 1.0147x over previous
#include <cuda_runtime.h>
#include <cuda_fp16.h>
#include <math.h>
#include <stdint.h>

// ---------------- problem constants ----------------
#define D_MODEL 1024
#define SEQ     2048
#define BATCH   8
#define CHUNK   16
#define NCHUNKS (SEQ / CHUNK)          // 128
#define ROWS    (SEQ * BATCH)          // 16384
#define STEP_ROWS (NCHUNKS * BATCH)    // 1024 rows per timestep

// ---------------- device scratch (no allocs allowed) ----------------
__device__ float  g_XA [ROWS * D_MODEL];        // x @ A^T           (P-layout, fp32)
__device__ float  g_SEL[ROWS * D_MODEL];        // sigmoid(xW+b)     (P-layout, fp32)
__device__ __half g_H  [ROWS * D_MODEL];        // hidden states     (P-layout, fp16)
__device__ float  g_Y  [ROWS * D_MODEL];        // H @ C^T           (P-layout, fp32)
__device__ __half g_Xh [ROWS * D_MODEL];        // fp16 copy of x    (g-layout)
__device__ __half g_Ah [D_MODEL * D_MODEL];
__device__ __half g_Bh [D_MODEL * D_MODEL];
__device__ __half g_Ch [D_MODEL * D_MODEL];
__device__ __half g_Wh [D_MODEL * D_MODEL];
__device__ unsigned g_bar;                      // grid-barrier ticket counter

// P-layout: row p = t*1024 + chunk*8 + b  for original row g = (chunk*16+t)*8+b
__device__ __forceinline__ int perm_row(int g) {
    int t = (g >> 3) & 15;
    int c = g >> 7;
    int b = g & 7;
    return t * STEP_ROWS + c * 8 + b;
}

__device__ __forceinline__ float sigm(float v) { return 1.0f / (1.0f + __expf(-v)); }

__device__ __forceinline__ uint32_t smem_u32(const void* p) {
    uint32_t a;
    asm("{ .reg .u64 t; cvta.to.shared.u64 t, %1; cvt.u32.u64 %0, t; }" : "=r"(a) : "l"(p));
    return a;
}

__device__ __forceinline__ uint32_t swz(uint32_t o) { return o ^ ((o >> 3) & 0x70); }

__device__ __forceinline__ void ldm_x4(uint32_t* r, uint32_t addr) {
    asm volatile("ldmatrix.sync.aligned.m8n8.x4.shared.b16 {%0,%1,%2,%3}, [%4];"
                 : "=r"(r[0]), "=r"(r[1]), "=r"(r[2]), "=r"(r[3]) : "r"(addr));
}

__device__ __forceinline__ void mma16816(float* c, const uint32_t* a, const uint32_t* b) {
    asm volatile(
        "mma.sync.aligned.m16n8k16.row.col.f32.f16.f16.f32 "
        "{%0,%1,%2,%3}, {%4,%5,%6,%7}, {%8,%9}, {%0,%1,%2,%3};"
        : "+f"(c[0]), "+f"(c[1]), "+f"(c[2]), "+f"(c[3])
        : "r"(a[0]), "r"(a[1]), "r"(a[2]), "r"(a[3]), "r"(b[0]), "r"(b[1]));
}

// Ticket grid barrier: replay-safe (counter only increases). Exactly GRID=128
// increments per instance; instances cleanly separated.
__device__ __forceinline__ void grid_bar() {
    __threadfence();
    __syncthreads();
    if (threadIdx.x == 0) {
        unsigned old = atomicAdd(&g_bar, 1u);
        unsigned target = (old & ~127u) + 128u;
        unsigned cur;
        do {
            asm volatile("ld.volatile.global.u32 %0, [%1];" : "=r"(cur) : "l"(&g_bar));
        } while (cur < target);
    }
    __syncthreads();
}

// ---------------- shared GEMM building blocks ----------------
enum { EPI_NONE = 0, EPI_PERM = 1, EPI_SIG_BIAS_PERM = 2 };

#define STAGES 3
#define B_TILE_BYTES 16384

template <int BM>
__device__ __forceinline__ void load_tile(
    uint32_t sb, int s, const __half* __restrict__ Aop, const __half* __restrict__ Bop,
    int m0, int n0, int kt, int tid)
{
    constexpr int A_TILE_BYTES = BM * 128;
    #pragma unroll
    for (int r = 0; r < (BM * 8) / 256; ++r) {
        int i   = tid + r * 256;
        int row = i >> 3;
        int cc  = i & 7;
        uint32_t sw = swz(row * 128 + cc * 16);
        const __half* ga = Aop + (size_t)(m0 + row) * D_MODEL + kt * 64 + cc * 8;
        asm volatile("cp.async.cg.shared.global [%0], [%1], 16;"
                     :: "r"(sb + s * A_TILE_BYTES + sw), "l"(ga));
    }
    #pragma unroll
    for (int r = 0; r < 4; ++r) {
        int i   = tid + r * 256;
        int row = i >> 3;
        int cc  = i & 7;
        uint32_t sw = swz(row * 128 + cc * 16);
        const __half* gb = Bop + (size_t)(n0 + row) * D_MODEL + kt * 64 + cc * 8;
        asm volatile("cp.async.cg.shared.global [%0], [%1], 16;"
                     :: "r"(sb + STAGES * A_TILE_BYTES + s * B_TILE_BYTES + sw), "l"(gb));
    }
    asm volatile("cp.async.commit_group;" ::: "memory");
}

// 3-stage smem pipeline, single-buffered register fragments. acc[MT][8][4].
template <int BM, int MT>
__device__ __forceinline__ void gemm_mainloop(
    uint32_t sb, const __half* __restrict__ Aop, const __half* __restrict__ Bop,
    int m0, int n0, int tid, float (*acc)[8][4])
{
    constexpr int A_TILE_BYTES = BM * 128;
    const int wid = tid >> 5, lid = tid & 31;
    const int warp_m = wid & 3;
    const int warp_n = wid >> 2;

    const int a_row = warp_m * (BM / 4) + (lid & 15);
    const int a_kb  = (lid >> 4) * 16;
    const int b_g   = lid >> 3;
    const int b_row = warp_n * 64 + ((b_g >= 2) ? 8 : 0) + (lid & 7);
    const int b_kb  = (b_g & 1) * 16;

    load_tile<BM>(sb, 0, Aop, Bop, m0, n0, 0, tid);
    load_tile<BM>(sb, 1, Aop, Bop, m0, n0, 1, tid);

    #pragma unroll 1
    for (int kt = 0; kt < 16; ++kt) {
        const int s = kt % STAGES;
        asm volatile("cp.async.wait_group 1;" ::: "memory");
        __syncthreads();
        if (kt + 2 < 16)
            load_tile<BM>(sb, (kt + 2) % STAGES, Aop, Bop, m0, n0, kt + 2, tid);
        else
            asm volatile("cp.async.commit_group;" ::: "memory");

        const uint32_t sA = sb + s * A_TILE_BYTES;
        const uint32_t sB = sb + STAGES * A_TILE_BYTES + s * B_TILE_BYTES;

        #pragma unroll
        for (int ks = 0; ks < 4; ++ks) {
            uint32_t af[MT][4];
            #pragma unroll
            for (int mt = 0; mt < MT; ++mt)
                ldm_x4(af[mt], sA + swz((a_row + mt * 16) * 128 + ks * 32 + a_kb));
            uint32_t bf[8][2];
            #pragma unroll
            for (int jp = 0; jp < 4; ++jp) {
                uint32_t t4[4];
                ldm_x4(t4, sB + swz((b_row + jp * 16) * 128 + ks * 32 + b_kb));
                bf[2 * jp + 0][0] = t4[0]; bf[2 * jp + 0][1] = t4[1];
                bf[2 * jp + 1][0] = t4[2]; bf[2 * jp + 1][1] = t4[3];
            }
            #pragma unroll
            for (int mt = 0; mt < MT; ++mt)
                #pragma unroll
                for (int nt = 0; nt < 8; ++nt)
                    mma16816(acc[mt][nt], af[mt], bf[nt]);
        }
    }
    __syncthreads();
}

// ---------------- big GEMM kernel (BM=128, BN=128) ----------------
template <int MODE>
__global__ void __launch_bounds__(256) tc_gemm(
    const __half* __restrict__ Aop,
    const __half* __restrict__ Bop,
    float*        __restrict__ out_f,
    const float*  __restrict__ bias)
{
    extern __shared__ __align__(1024) char smem[];
    const uint32_t sb = smem_u32(smem);
    const int tid = threadIdx.x, wid = tid >> 5, lid = tid & 31;
    const int m0 = blockIdx.y * 128, n0 = blockIdx.x * 128;
    const int warp_m = wid & 3, warp_n = wid >> 2;

    float acc[2][8][4];
    #pragma unroll
    for (int mt = 0; mt < 2; ++mt)
        #pragma unroll
        for (int nt = 0; nt < 8; ++nt)
            #pragma unroll
            for (int e = 0; e < 4; ++e) acc[mt][nt][e] = 0.0f;

    gemm_mainloop<128, 2>(sb, Aop, Bop, m0, n0, tid, acc);

    const int er0 = warp_m * 32 + (lid >> 2);
    const int ec  = warp_n * 64 + (lid & 3) * 2;

    #pragma unroll
    for (int mt = 0; mt < 2; ++mt) {
        #pragma unroll
        for (int half = 0; half < 2; ++half) {
            const int row = m0 + er0 + mt * 16 + half * 8;
            int orow = row;
            if constexpr (MODE == EPI_PERM || MODE == EPI_SIG_BIAS_PERM)
                orow = perm_row(row);
            #pragma unroll
            for (int nt = 0; nt < 8; ++nt) {
                const int col = n0 + ec + nt * 8;
                float v0 = acc[mt][nt][2 * half + 0];
                float v1 = acc[mt][nt][2 * half + 1];
                if constexpr (MODE == EPI_SIG_BIAS_PERM) {
                    const float2 bb = *(const float2*)(bias + col);
                    v0 = sigm(v0 + bb.x);
                    v1 = sigm(v1 + bb.y);
                }
                *(float2*)(out_f + (size_t)orow * D_MODEL + col) = make_float2(v0, v1);
            }
        }
    }
}

#define SMEM_BIG  (STAGES * (128 * 128 + B_TILE_BYTES))   // 98304

// ---------------- persistent recurrence kernel (B resident in smem) ----------------
// 128 CTAs. CTA: rows m0..m0+127 (8 m-blocks), cols n0..n0+63 (16 n-blocks).
// B slice (64 rows x 1024 K = 128KB) loaded into smem ONCE, reused for all 15
// steps; only A (= H[t-1]) tiles stream through a 3-stage pipeline.
#define REC_A_TILE 16384                       // 128 rows x 128B
#define REC_B_CHUNK 8192                       // 64 rows x 128B per k-tile
#define SMEM_REC (STAGES * REC_A_TILE + 16 * REC_B_CHUNK)   // 180224

__global__ void __launch_bounds__(256) rec_kernel(
    const __half* __restrict__ Bop,
    __half*       __restrict__ H,
    const float*  __restrict__ XA,
    const float*  __restrict__ SEL)
{
    extern __shared__ __align__(1024) char smem[];
    const uint32_t sb  = smem_u32(smem);
    const uint32_t sbB = sb + STAGES * REC_A_TILE;
    const int tid = threadIdx.x, wid = tid >> 5, lid = tid & 31;
    const int n0 = (blockIdx.x & 15) * 64;
    const int m0 = (blockIdx.x >> 4) * 128;
    const int warp_m = wid & 3, warp_n = wid >> 2;

    // ---- one-time B slice load into smem (cp.async, overlapped with h0) ----
    #pragma unroll 4
    for (int i = tid; i < 8192; i += 256) {      // 8192 x 16B = 128KB
        int kt = i >> 9;                          // 0..15
        int r  = (i >> 3) & 63;                   // row in slice
        int cc = i & 7;
        const __half* gb = Bop + (size_t)(n0 + r) * D_MODEL + kt * 64 + cc * 8;
        uint32_t dst = sbB + kt * REC_B_CHUNK + swz(r * 128 + cc * 16);
        asm volatile("cp.async.cg.shared.global [%0], [%1], 16;" :: "r"(dst), "l"(gb));
    }
    asm volatile("cp.async.commit_group;" ::: "memory");

    // ---- t = 0: elementwise h0 on this CTA's 128x64 patch ----
    #pragma unroll
    for (int r = 0; r < 8; ++r) {
        int i = tid + r * 256;          // 0..2047 float4s
        int row = m0 + (i >> 4);
        int col = n0 + (i & 15) * 4;
        size_t idx = (size_t)row * D_MODEL + col;
        const float4 xa = *(const float4*)(XA + idx);
        const float4 sv = *(const float4*)(SEL + idx);
        __half h[4];
        h[0] = __float2half(tanhf(xa.x) * sv.x);
        h[1] = __float2half(tanhf(xa.y) * sv.y);
        h[2] = __float2half(tanhf(xa.z) * sv.z);
        h[3] = __float2half(tanhf(xa.w) * sv.w);
        *(uint2*)(H + idx) = *(uint2*)h;
    }

    asm volatile("cp.async.wait_group 0;" ::: "memory");
    __syncthreads();
    grid_bar();

    // ---- ldmatrix / epilogue lane addressing ----
    const int a_row = warp_m * 32 + (lid & 15);       // + mt*16
    const int a_kb  = (lid >> 4) * 16;
    const int b_g   = lid >> 3;
    const int b_row = warp_n * 32 + ((b_g >= 2) ? 8 : 0) + (lid & 7);  // + jp*16
    const int b_kb  = (b_g & 1) * 16;
    const int er0 = warp_m * 32 + (lid >> 2);
    const int ec  = warp_n * 32 + (lid & 3) * 2;

    #pragma unroll 1
    for (int t = 1; t < CHUNK; ++t) {
        const __half* Aprev = H + (size_t)(t - 1) * STEP_ROWS * D_MODEL;

        float acc[2][4][4];
        #pragma unroll
        for (int mt = 0; mt < 2; ++mt)
            #pragma unroll
            for (int nt = 0; nt < 4; ++nt)
                #pragma unroll
                for (int e = 0; e < 4; ++e) acc[mt][nt][e] = 0.0f;

        // A-only 3-stage pipeline
        auto load_a = [&](int s, int kt) {
            #pragma unroll
            for (int r = 0; r < 4; ++r) {
                int i   = tid + r * 256;
                int row = i >> 3;
                int cc  = i & 7;
                const __half* ga = Aprev + (size_t)(m0 + row) * D_MODEL + kt * 64 + cc * 8;
                uint32_t dst = sb + s * REC_A_TILE + swz(row * 128 + cc * 16);
                asm volatile("cp.async.cg.shared.global [%0], [%1], 16;" :: "r"(dst), "l"(ga));
            }
            asm volatile("cp.async.commit_group;" ::: "memory");
        };

        load_a(0, 0);
        load_a(1, 1);

        #pragma unroll 1
        for (int kt = 0; kt < 16; ++kt) {
            const int s = kt % STAGES;
            asm volatile("cp.async.wait_group 1;" ::: "memory");
            __syncthreads();
            if (kt + 2 < 16)
                load_a((kt + 2) % STAGES, kt + 2);
            else
                asm volatile("cp.async.commit_group;" ::: "memory");

            const uint32_t sA  = sb + s * REC_A_TILE;
            const uint32_t sBk = sbB + kt * REC_B_CHUNK;

            #pragma unroll
            for (int ks = 0; ks < 4; ++ks) {
                uint32_t af[2][4];
                #pragma unroll
                for (int mt = 0; mt < 2; ++mt)
                    ldm_x4(af[mt], sA + swz((a_row + mt * 16) * 128 + ks * 32 + a_kb));
                uint32_t bf[4][2];
                #pragma unroll
                for (int jp = 0; jp < 2; ++jp) {
                    uint32_t t4[4];
                    ldm_x4(t4, sBk + swz((b_row + jp * 16) * 128 + ks * 32 + b_kb));
                    bf[2 * jp + 0][0] = t4[0]; bf[2 * jp + 0][1] = t4[1];
                    bf[2 * jp + 1][0] = t4[2]; bf[2 * jp + 1][1] = t4[3];
                }
                #pragma unroll
                for (int mt = 0; mt < 2; ++mt)
                    #pragma unroll
                    for (int nt = 0; nt < 4; ++nt)
                        mma16816(acc[mt][nt], af[mt], bf[nt]);
            }
        }
        __syncthreads();

        // epilogue: h = tanh(acc + xa)*sel -> H[t] (fp16), 128x64 patch
        const size_t base = (size_t)t * STEP_ROWS * D_MODEL;
        #pragma unroll
        for (int mt = 0; mt < 2; ++mt) {
            #pragma unroll
            for (int half = 0; half < 2; ++half) {
                const int row = m0 + er0 + mt * 16 + half * 8;
                #pragma unroll
                for (int nt = 0; nt < 4; ++nt) {
                    const int col = n0 + ec + nt * 8;
                    const size_t idx = base + (size_t)row * D_MODEL + col;
                    const float2 av = *(const float2*)(XA + idx);
                    const float2 sv = *(const float2*)(SEL + idx);
                    __half2 hv;
                    hv.x = __float2half(tanhf(acc[mt][nt][2 * half + 0] + av.x) * sv.x);
                    hv.y = __float2half(tanhf(acc[mt][nt][2 * half + 1] + av.y) * sv.y);
                    *(__half2*)(H + idx) = hv;
                }
            }
        }
        if (t < CHUNK - 1) grid_bar();
    }
}

// ---------------- fp32 -> fp16 conversions ----------------
__global__ void __launch_bounds__(256) f2h_kernel(const float* __restrict__ s,
                                                  __half* __restrict__ d)
{
    const int i = blockIdx.x * blockDim.x + threadIdx.x;
    const float4 v = ((const float4*)s)[i];
    __half h[4];
    h[0] = __float2half(v.x); h[1] = __float2half(v.y);
    h[2] = __float2half(v.z); h[3] = __float2half(v.w);
    ((uint2*)d)[i] = *(uint2*)h;
}

// all 4 weight matrices in one launch: blockIdx.x>>10 selects the matrix
__global__ void __launch_bounds__(256) f2h_w4_kernel(
    const float* __restrict__ s0, __half* __restrict__ d0,
    const float* __restrict__ s1, __half* __restrict__ d1,
    const float* __restrict__ s2, __half* __restrict__ d2,
    const float* __restrict__ s3, __half* __restrict__ d3)
{
    const int m = blockIdx.x >> 10;                 // 0..3
    const int i = (blockIdx.x & 1023) * blockDim.x + threadIdx.x;
    const float* s = (m == 0) ? s0 : (m == 1) ? s1 : (m == 2) ? s2 : s3;
    __half*      d = (m == 0) ? d0 : (m == 1) ? d1 : (m == 2) ? d2 : d3;
    const float4 v = ((const float4*)s)[i];
    __half h[4];
    h[0] = __float2half(v.x); h[1] = __float2half(v.y);
    h[2] = __float2half(v.z); h[3] = __float2half(v.w);
    ((uint2*)d)[i] = *(uint2*)h;
}

// Per output row g: y = Y_P[perm(g)] + x[g]*D, then LayerNorm -> out[g]
__global__ void __launch_bounds__(256) ln_kernel(
    const float* __restrict__ Y,
    const float* __restrict__ x,
    const float* __restrict__ Dv,
    const float* __restrict__ gamma,
    const float* __restrict__ beta,
    float* __restrict__ out)
{
    const int g = blockIdx.x;
    const int t = (g >> 3) & 15;
    const int c = g >> 7;
    const int b = g & 7;
    const int prow = t * STEP_ROWS + c * 8 + b;

    const int j = threadIdx.x * 4;
    const float4 yv = *(const float4*)(Y  + (size_t)prow * D_MODEL + j);
    const float4 xv = *(const float4*)(x  + (size_t)g    * D_MODEL + j);
    const float4 dv = *(const float4*)(Dv + j);

    float y0 = yv.x + xv.x * dv.x;
    float y1 = yv.y + xv.y * dv.y;
    float y2 = yv.z + xv.z * dv.z;
    float y3 = yv.w + xv.w * dv.w;

    float s  = y0 + y1 + y2 + y3;
    float ss = y0 * y0 + y1 * y1 + y2 * y2 + y3 * y3;

    #pragma unroll
    for (int off = 16; off; off >>= 1) {
        s  += __shfl_xor_sync(0xffffffffu, s,  off);
        ss += __shfl_xor_sync(0xffffffffu, ss, off);
    }
    __shared__ float sh_s[8], sh_ss[8];
    const int w = threadIdx.x >> 5, l = threadIdx.x & 31;
    if (l == 0) { sh_s[w] = s; sh_ss[w] = ss; }
    __syncthreads();
    if (w == 0) {
        s  = (l < 8) ? sh_s[l]  : 0.0f;
        ss = (l < 8) ? sh_ss[l] : 0.0f;
        #pragma unroll
        for (int off = 4; off; off >>= 1) {
            s  += __shfl_xor_sync(0xffffffffu, s,  off);
            ss += __shfl_xor_sync(0xffffffffu, ss, off);
        }
        if (l == 0) { sh_s[0] = s; sh_ss[0] = ss; }
    }
    __syncthreads();
    const float mean = sh_s[0] * (1.0f / D_MODEL);
    const float var  = sh_ss[0] * (1.0f / D_MODEL) - mean * mean;
    const float inv  = rsqrtf(var + 1e-5f);

    const float4 gm = *(const float4*)(gamma + j);
    const float4 bt = *(const float4*)(beta  + j);
    float4 o;
    o.x = (y0 - mean) * inv * gm.x + bt.x;
    o.y = (y1 - mean) * inv * gm.y + bt.y;
    o.z = (y2 - mean) * inv * gm.z + bt.z;
    o.w = (y3 - mean) * inv * gm.w + bt.w;
    *(float4*)(out + (size_t)g * D_MODEL + j) = o;
}

// ---------------- launch ----------------
extern "C" void kernel_launch(void* const* d_in, const int* in_sizes, int n_in,
                              void* d_out, int out_size)
{
    (void)in_sizes; (void)n_in; (void)out_size;
    const float* x     = (const float*)d_in[0];
    const float* A     = (const float*)d_in[1];
    const float* B     = (const float*)d_in[2];
    const float* C     = (const float*)d_in[3];
    const float* Dv    = (const float*)d_in[4];
    const float* W_sel = (const float*)d_in[5];
    const float* b_sel = (const float*)d_in[6];
    const float* gamma = (const float*)d_in[7];
    const float* beta  = (const float*)d_in[8];
    float* out = (float*)d_out;

    float *XA, *SEL, *Y;
    __half *H, *Xh, *Ah, *Bh, *Ch, *Wh;
    cudaGetSymbolAddress((void**)&XA,  g_XA);
    cudaGetSymbolAddress((void**)&SEL, g_SEL);
    cudaGetSymbolAddress((void**)&H,   g_H);
    cudaGetSymbolAddress((void**)&Y,   g_Y);
    cudaGetSymbolAddress((void**)&Xh,  g_Xh);
    cudaGetSymbolAddress((void**)&Ah,  g_Ah);
    cudaGetSymbolAddress((void**)&Bh,  g_Bh);
    cudaGetSymbolAddress((void**)&Ch,  g_Ch);
    cudaGetSymbolAddress((void**)&Wh,  g_Wh);

    cudaFuncSetAttribute(tc_gemm<EPI_NONE>,          cudaFuncAttributeMaxDynamicSharedMemorySize, SMEM_BIG);
    cudaFuncSetAttribute(tc_gemm<EPI_PERM>,          cudaFuncAttributeMaxDynamicSharedMemorySize, SMEM_BIG);
    cudaFuncSetAttribute(tc_gemm<EPI_SIG_BIAS_PERM>, cudaFuncAttributeMaxDynamicSharedMemorySize, SMEM_BIG);
    cudaFuncSetAttribute(rec_kernel,                 cudaFuncAttributeMaxDynamicSharedMemorySize, SMEM_REC);

    // launch 1: x -> fp16
    f2h_kernel<<<(ROWS * D_MODEL / 4) / 256, 256>>>(x, Xh);
    // launch 2: all 4 weight matrices -> fp16 (one kernel)
    f2h_w4_kernel<<<4096, 256>>>(A, Ah, B, Bh, C, Ch, W_sel, Wh);

    const dim3 big_grid(D_MODEL / 128, ROWS / 128);        // 8 x 128

    // launch 3: SEL = sigmoid(x @ Wsel^T + b)  (P-layout fp32)
    tc_gemm<EPI_SIG_BIAS_PERM><<<big_grid, 256, SMEM_BIG>>>(Xh, Wh, SEL, b_sel);
    // launch 4: XA = x @ A^T  (P-layout fp32)
    tc_gemm<EPI_PERM><<<big_grid, 256, SMEM_BIG>>>(Xh, Ah, XA, nullptr);
    // launch 5: full recurrence (h0 + 15 steps), persistent, B resident in smem
    rec_kernel<<<128, 256, SMEM_REC>>>(Bh, H, XA, SEL);
    // launch 6: Y = H @ C^T  (P-layout fp32)
    tc_gemm<EPI_NONE><<<big_grid, 256, SMEM_BIG>>>(H, Ch, Y, nullptr);
    // launch 7: LayerNorm + x*D + un-permute
    ln_kernel<<<ROWS, 256>>>(Y, x, Dv, gamma, beta, out);
}

// round 13
// speedup vs baseline: 1.2154x; 1.0213x over previous
#include <cuda_runtime.h>
#include <cuda_fp16.h>
#include <math.h>
#include <stdint.h>

// ---------------- problem constants ----------------
#define D_MODEL 1024
#define SEQ     2048
#define BATCH   8
#define CHUNK   16
#define NCHUNKS (SEQ / CHUNK)          // 128
#define ROWS    (SEQ * BATCH)          // 16384
#define STEP_ROWS (NCHUNKS * BATCH)    // 1024 rows per timestep

// ---------------- device scratch (no allocs allowed) ----------------
__device__ float  g_XA [ROWS * D_MODEL];        // x @ A^T           (P-layout, fp32)
__device__ float  g_SEL[ROWS * D_MODEL];        // sigmoid(xW+b)     (P-layout, fp32)
__device__ __half g_H  [ROWS * D_MODEL];        // hidden states     (P-layout, fp16)
__device__ float  g_Y  [ROWS * D_MODEL];        // H @ C^T           (P-layout, fp32)
__device__ __half g_Xh [ROWS * D_MODEL];        // fp16 copy of x    (g-layout)
__device__ __half g_Ah [D_MODEL * D_MODEL];
__device__ __half g_Bh [D_MODEL * D_MODEL];
__device__ __half g_Ch [D_MODEL * D_MODEL];
__device__ __half g_Wh [D_MODEL * D_MODEL];
__device__ unsigned g_mgbar[8 * 32];            // per-m-group ticket counters (128B apart)

// P-layout: row p = t*1024 + chunk*8 + b  for original row g = (chunk*16+t)*8+b
__device__ __forceinline__ int perm_row(int g) {
    int t = (g >> 3) & 15;
    int c = g >> 7;
    int b = g & 7;
    return t * STEP_ROWS + c * 8 + b;
}

__device__ __forceinline__ float sigm(float v) { return 1.0f / (1.0f + __expf(-v)); }

__device__ __forceinline__ uint32_t smem_u32(const void* p) {
    uint32_t a;
    asm("{ .reg .u64 t; cvta.to.shared.u64 t, %1; cvt.u32.u64 %0, t; }" : "=r"(a) : "l"(p));
    return a;
}

__device__ __forceinline__ uint32_t swz(uint32_t o) { return o ^ ((o >> 3) & 0x70); }

__device__ __forceinline__ void ldm_x4(uint32_t* r, uint32_t addr) {
    asm volatile("ldmatrix.sync.aligned.m8n8.x4.shared.b16 {%0,%1,%2,%3}, [%4];"
                 : "=r"(r[0]), "=r"(r[1]), "=r"(r[2]), "=r"(r[3]) : "r"(addr));
}

__device__ __forceinline__ void mma16816(float* c, const uint32_t* a, const uint32_t* b) {
    asm volatile(
        "mma.sync.aligned.m16n8k16.row.col.f32.f16.f16.f32 "
        "{%0,%1,%2,%3}, {%4,%5,%6,%7}, {%8,%9}, {%0,%1,%2,%3};"
        : "+f"(c[0]), "+f"(c[1]), "+f"(c[2]), "+f"(c[3])
        : "r"(a[0]), "r"(a[1]), "r"(a[2]), "r"(a[3]), "r"(b[0]), "r"(b[1]));
}

// Per-m-group ticket barrier: 16 CTAs per group, monotonic counter, replay-safe
// (exactly 16 increments per instance; instances cleanly separated per group).
__device__ __forceinline__ void group_bar(int mg) {
    __threadfence();
    __syncthreads();
    if (threadIdx.x == 0) {
        unsigned* ctr = &g_mgbar[mg * 32];
        unsigned old = atomicAdd(ctr, 1u);
        unsigned target = (old & ~15u) + 16u;
        unsigned cur;
        do {
            asm volatile("ld.volatile.global.u32 %0, [%1];" : "=r"(cur) : "l"(ctr));
        } while (cur < target);
    }
    __syncthreads();
}

// ---------------- shared GEMM building blocks ----------------
enum { EPI_NONE = 0, EPI_PERM = 1, EPI_SIG_BIAS_PERM = 2 };

#define STAGES 3
#define B_TILE_BYTES 16384

template <int BM>
__device__ __forceinline__ void load_tile(
    uint32_t sb, int s, const __half* __restrict__ Aop, const __half* __restrict__ Bop,
    int m0, int n0, int kt, int tid)
{
    constexpr int A_TILE_BYTES = BM * 128;
    #pragma unroll
    for (int r = 0; r < (BM * 8) / 256; ++r) {
        int i   = tid + r * 256;
        int row = i >> 3;
        int cc  = i & 7;
        uint32_t sw = swz(row * 128 + cc * 16);
        const __half* ga = Aop + (size_t)(m0 + row) * D_MODEL + kt * 64 + cc * 8;
        asm volatile("cp.async.cg.shared.global [%0], [%1], 16;"
                     :: "r"(sb + s * A_TILE_BYTES + sw), "l"(ga));
    }
    #pragma unroll
    for (int r = 0; r < 4; ++r) {
        int i   = tid + r * 256;
        int row = i >> 3;
        int cc  = i & 7;
        uint32_t sw = swz(row * 128 + cc * 16);
        const __half* gb = Bop + (size_t)(n0 + row) * D_MODEL + kt * 64 + cc * 8;
        asm volatile("cp.async.cg.shared.global [%0], [%1], 16;"
                     :: "r"(sb + STAGES * A_TILE_BYTES + s * B_TILE_BYTES + sw), "l"(gb));
    }
    asm volatile("cp.async.commit_group;" ::: "memory");
}

// 3-stage smem pipeline, single-buffered register fragments. acc[MT][8][4].
template <int BM, int MT>
__device__ __forceinline__ void gemm_mainloop(
    uint32_t sb, const __half* __restrict__ Aop, const __half* __restrict__ Bop,
    int m0, int n0, int tid, float (*acc)[8][4])
{
    constexpr int A_TILE_BYTES = BM * 128;
    const int wid = tid >> 5, lid = tid & 31;
    const int warp_m = wid & 3;
    const int warp_n = wid >> 2;

    const int a_row = warp_m * (BM / 4) + (lid & 15);
    const int a_kb  = (lid >> 4) * 16;
    const int b_g   = lid >> 3;
    const int b_row = warp_n * 64 + ((b_g >= 2) ? 8 : 0) + (lid & 7);
    const int b_kb  = (b_g & 1) * 16;

    load_tile<BM>(sb, 0, Aop, Bop, m0, n0, 0, tid);
    load_tile<BM>(sb, 1, Aop, Bop, m0, n0, 1, tid);

    #pragma unroll 1
    for (int kt = 0; kt < 16; ++kt) {
        const int s = kt % STAGES;
        asm volatile("cp.async.wait_group 1;" ::: "memory");
        __syncthreads();
        if (kt + 2 < 16)
            load_tile<BM>(sb, (kt + 2) % STAGES, Aop, Bop, m0, n0, kt + 2, tid);
        else
            asm volatile("cp.async.commit_group;" ::: "memory");

        const uint32_t sA = sb + s * A_TILE_BYTES;
        const uint32_t sB = sb + STAGES * A_TILE_BYTES + s * B_TILE_BYTES;

        #pragma unroll
        for (int ks = 0; ks < 4; ++ks) {
            uint32_t af[MT][4];
            #pragma unroll
            for (int mt = 0; mt < MT; ++mt)
                ldm_x4(af[mt], sA + swz((a_row + mt * 16) * 128 + ks * 32 + a_kb));
            uint32_t bf[8][2];
            #pragma unroll
            for (int jp = 0; jp < 4; ++jp) {
                uint32_t t4[4];
                ldm_x4(t4, sB + swz((b_row + jp * 16) * 128 + ks * 32 + b_kb));
                bf[2 * jp + 0][0] = t4[0]; bf[2 * jp + 0][1] = t4[1];
                bf[2 * jp + 1][0] = t4[2]; bf[2 * jp + 1][1] = t4[3];
            }
            #pragma unroll
            for (int mt = 0; mt < MT; ++mt)
                #pragma unroll
                for (int nt = 0; nt < 8; ++nt)
                    mma16816(acc[mt][nt], af[mt], bf[nt]);
        }
    }
    __syncthreads();
}

// ---------------- big GEMM kernel (BM=128, BN=128) ----------------
template <int MODE>
__global__ void __launch_bounds__(256) tc_gemm(
    const __half* __restrict__ Aop,
    const __half* __restrict__ Bop,
    float*        __restrict__ out_f,
    const float*  __restrict__ bias)
{
    extern __shared__ __align__(1024) char smem[];
    const uint32_t sb = smem_u32(smem);
    const int tid = threadIdx.x, wid = tid >> 5, lid = tid & 31;
    const int m0 = blockIdx.y * 128, n0 = blockIdx.x * 128;
    const int warp_m = wid & 3, warp_n = wid >> 2;

    float acc[2][8][4];
    #pragma unroll
    for (int mt = 0; mt < 2; ++mt)
        #pragma unroll
        for (int nt = 0; nt < 8; ++nt)
            #pragma unroll
            for (int e = 0; e < 4; ++e) acc[mt][nt][e] = 0.0f;

    gemm_mainloop<128, 2>(sb, Aop, Bop, m0, n0, tid, acc);

    const int er0 = warp_m * 32 + (lid >> 2);
    const int ec  = warp_n * 64 + (lid & 3) * 2;

    #pragma unroll
    for (int mt = 0; mt < 2; ++mt) {
        #pragma unroll
        for (int half = 0; half < 2; ++half) {
            const int row = m0 + er0 + mt * 16 + half * 8;
            int orow = row;
            if constexpr (MODE == EPI_PERM || MODE == EPI_SIG_BIAS_PERM)
                orow = perm_row(row);
            #pragma unroll
            for (int nt = 0; nt < 8; ++nt) {
                const int col = n0 + ec + nt * 8;
                float v0 = acc[mt][nt][2 * half + 0];
                float v1 = acc[mt][nt][2 * half + 1];
                if constexpr (MODE == EPI_SIG_BIAS_PERM) {
                    const float2 bb = *(const float2*)(bias + col);
                    v0 = sigm(v0 + bb.x);
                    v1 = sigm(v1 + bb.y);
                }
                *(float2*)(out_f + (size_t)orow * D_MODEL + col) = make_float2(v0, v1);
            }
        }
    }
}

#define SMEM_BIG  (STAGES * (128 * 128 + B_TILE_BYTES))   // 98304

// ---------------- persistent recurrence kernel ----------------
// 128 CTAs = 8 m-groups x 16 n-slices. B slice (64x1024 = 128KB) resident in
// smem; A (= H[t-1] rows of own m-group) streams through a 5-stage pipeline.
// Cross-step sync is per-m-group (16 CTAs), not grid-wide.
#define REC_STAGES 5
#define REC_A_TILE 16384                       // 128 rows x 128B
#define REC_B_CHUNK 8192                       // 64 rows x 128B per k-tile
#define SMEM_REC (REC_STAGES * REC_A_TILE + 16 * REC_B_CHUNK)   // 212992

__global__ void __launch_bounds__(256) rec_kernel(
    const __half* __restrict__ Bop,
    __half*       __restrict__ H,
    const float*  __restrict__ XA,
    const float*  __restrict__ SEL)
{
    extern __shared__ __align__(1024) char smem[];
    const uint32_t sb  = smem_u32(smem);
    const uint32_t sbB = sb + REC_STAGES * REC_A_TILE;
    const int tid = threadIdx.x, wid = tid >> 5, lid = tid & 31;
    const int n0 = (blockIdx.x & 15) * 64;
    const int mg = blockIdx.x >> 4;
    const int m0 = mg * 128;
    const int warp_m = wid & 3, warp_n = wid >> 2;

    // ---- one-time B slice load into smem (cp.async, overlapped with h0) ----
    #pragma unroll 4
    for (int i = tid; i < 8192; i += 256) {      // 8192 x 16B = 128KB
        int kt = i >> 9;                          // 0..15
        int r  = (i >> 3) & 63;                   // row in slice
        int cc = i & 7;
        const __half* gb = Bop + (size_t)(n0 + r) * D_MODEL + kt * 64 + cc * 8;
        uint32_t dst = sbB + kt * REC_B_CHUNK + swz(r * 128 + cc * 16);
        asm volatile("cp.async.cg.shared.global [%0], [%1], 16;" :: "r"(dst), "l"(gb));
    }
    asm volatile("cp.async.commit_group;" ::: "memory");

    // ---- t = 0: elementwise h0 on this CTA's 128x64 patch ----
    #pragma unroll
    for (int r = 0; r < 8; ++r) {
        int i = tid + r * 256;          // 0..2047 float4s
        int row = m0 + (i >> 4);
        int col = n0 + (i & 15) * 4;
        size_t idx = (size_t)row * D_MODEL + col;
        const float4 xa = *(const float4*)(XA + idx);
        const float4 sv = *(const float4*)(SEL + idx);
        __half h[4];
        h[0] = __float2half(tanhf(xa.x) * sv.x);
        h[1] = __float2half(tanhf(xa.y) * sv.y);
        h[2] = __float2half(tanhf(xa.z) * sv.z);
        h[3] = __float2half(tanhf(xa.w) * sv.w);
        *(uint2*)(H + idx) = *(uint2*)h;
    }

    asm volatile("cp.async.wait_group 0;" ::: "memory");
    __syncthreads();
    group_bar(mg);

    // ---- ldmatrix / epilogue lane addressing ----
    const int a_row = warp_m * 32 + (lid & 15);       // + mt*16
    const int a_kb  = (lid >> 4) * 16;
    const int b_g   = lid >> 3;
    const int b_row = warp_n * 32 + ((b_g >= 2) ? 8 : 0) + (lid & 7);  // + jp*16
    const int b_kb  = (b_g & 1) * 16;
    const int er0 = warp_m * 32 + (lid >> 2);
    const int ec  = warp_n * 32 + (lid & 3) * 2;

    #pragma unroll 1
    for (int t = 1; t < CHUNK; ++t) {
        const __half* Aprev = H + (size_t)(t - 1) * STEP_ROWS * D_MODEL;

        float acc[2][4][4];
        #pragma unroll
        for (int mt = 0; mt < 2; ++mt)
            #pragma unroll
            for (int nt = 0; nt < 4; ++nt)
                #pragma unroll
                for (int e = 0; e < 4; ++e) acc[mt][nt][e] = 0.0f;

        // A-only 5-stage pipeline
        auto load_a = [&](int s, int kt) {
            #pragma unroll
            for (int r = 0; r < 4; ++r) {
                int i   = tid + r * 256;
                int row = i >> 3;
                int cc  = i & 7;
                const __half* ga = Aprev + (size_t)(m0 + row) * D_MODEL + kt * 64 + cc * 8;
                uint32_t dst = sb + s * REC_A_TILE + swz(row * 128 + cc * 16);
                asm volatile("cp.async.cg.shared.global [%0], [%1], 16;" :: "r"(dst), "l"(ga));
            }
            asm volatile("cp.async.commit_group;" ::: "memory");
        };

        load_a(0, 0);
        load_a(1, 1);
        load_a(2, 2);
        load_a(3, 3);

        #pragma unroll 1
        for (int kt = 0; kt < 16; ++kt) {
            const int s = kt % REC_STAGES;
            asm volatile("cp.async.wait_group 3;" ::: "memory");
            __syncthreads();
            // refill slot (kt+4)%5 (== slot (kt-1)%5, consumed last iteration)
            if (kt + 4 < 16)
                load_a((kt + 4) % REC_STAGES, kt + 4);
            else
                asm volatile("cp.async.commit_group;" ::: "memory");

            const uint32_t sA  = sb + s * REC_A_TILE;
            const uint32_t sBk = sbB + kt * REC_B_CHUNK;

            #pragma unroll
            for (int ks = 0; ks < 4; ++ks) {
                uint32_t af[2][4];
                #pragma unroll
                for (int mt = 0; mt < 2; ++mt)
                    ldm_x4(af[mt], sA + swz((a_row + mt * 16) * 128 + ks * 32 + a_kb));
                uint32_t bf[4][2];
                #pragma unroll
                for (int jp = 0; jp < 2; ++jp) {
                    uint32_t t4[4];
                    ldm_x4(t4, sBk + swz((b_row + jp * 16) * 128 + ks * 32 + b_kb));
                    bf[2 * jp + 0][0] = t4[0]; bf[2 * jp + 0][1] = t4[1];
                    bf[2 * jp + 1][0] = t4[2]; bf[2 * jp + 1][1] = t4[3];
                }
                #pragma unroll
                for (int mt = 0; mt < 2; ++mt)
                    #pragma unroll
                    for (int nt = 0; nt < 4; ++nt)
                        mma16816(acc[mt][nt], af[mt], bf[nt]);
            }
        }
        __syncthreads();

        // epilogue: h = tanh(acc + xa)*sel -> H[t] (fp16), 128x64 patch
        const size_t base = (size_t)t * STEP_ROWS * D_MODEL;
        #pragma unroll
        for (int mt = 0; mt < 2; ++mt) {
            #pragma unroll
            for (int half = 0; half < 2; ++half) {
                const int row = m0 + er0 + mt * 16 + half * 8;
                #pragma unroll
                for (int nt = 0; nt < 4; ++nt) {
                    const int col = n0 + ec + nt * 8;
                    const size_t idx = base + (size_t)row * D_MODEL + col;
                    const float2 av = *(const float2*)(XA + idx);
                    const float2 sv = *(const float2*)(SEL + idx);
                    __half2 hv;
                    hv.x = __float2half(tanhf(acc[mt][nt][2 * half + 0] + av.x) * sv.x);
                    hv.y = __float2half(tanhf(acc[mt][nt][2 * half + 1] + av.y) * sv.y);
                    *(__half2*)(H + idx) = hv;
                }
            }
        }
        if (t < CHUNK - 1) group_bar(mg);
    }
}

// ---------------- fp32 -> fp16 conversions ----------------
__global__ void __launch_bounds__(256) f2h_kernel(const float* __restrict__ s,
                                                  __half* __restrict__ d)
{
    const int i = blockIdx.x * blockDim.x + threadIdx.x;
    const float4 v = ((const float4*)s)[i];
    __half h[4];
    h[0] = __float2half(v.x); h[1] = __float2half(v.y);
    h[2] = __float2half(v.z); h[3] = __float2half(v.w);
    ((uint2*)d)[i] = *(uint2*)h;
}

// all 4 weight matrices in one launch: blockIdx.x>>10 selects the matrix
__global__ void __launch_bounds__(256) f2h_w4_kernel(
    const float* __restrict__ s0, __half* __restrict__ d0,
    const float* __restrict__ s1, __half* __restrict__ d1,
    const float* __restrict__ s2, __half* __restrict__ d2,
    const float* __restrict__ s3, __half* __restrict__ d3)
{
    const int m = blockIdx.x >> 10;                 // 0..3
    const int i = (blockIdx.x & 1023) * blockDim.x + threadIdx.x;
    const float* s = (m == 0) ? s0 : (m == 1) ? s1 : (m == 2) ? s2 : s3;
    __half*      d = (m == 0) ? d0 : (m == 1) ? d1 : (m == 2) ? d2 : d3;
    const float4 v = ((const float4*)s)[i];
    __half h[4];
    h[0] = __float2half(v.x); h[1] = __float2half(v.y);
    h[2] = __float2half(v.z); h[3] = __float2half(v.w);
    ((uint2*)d)[i] = *(uint2*)h;
}

// Per output row g: y = Y_P[perm(g)] + x[g]*D, then LayerNorm -> out[g]
__global__ void __launch_bounds__(256) ln_kernel(
    const float* __restrict__ Y,
    const float* __restrict__ x,
    const float* __restrict__ Dv,
    const float* __restrict__ gamma,
    const float* __restrict__ beta,
    float* __restrict__ out)
{
    const int g = blockIdx.x;
    const int t = (g >> 3) & 15;
    const int c = g >> 7;
    const int b = g & 7;
    const int prow = t * STEP_ROWS + c * 8 + b;

    const int j = threadIdx.x * 4;
    const float4 yv = *(const float4*)(Y  + (size_t)prow * D_MODEL + j);
    const float4 xv = *(const float4*)(x  + (size_t)g    * D_MODEL + j);
    const float4 dv = *(const float4*)(Dv + j);

    float y0 = yv.x + xv.x * dv.x;
    float y1 = yv.y + xv.y * dv.y;
    float y2 = yv.z + xv.z * dv.z;
    float y3 = yv.w + xv.w * dv.w;

    float s  = y0 + y1 + y2 + y3;
    float ss = y0 * y0 + y1 * y1 + y2 * y2 + y3 * y3;

    #pragma unroll
    for (int off = 16; off; off >>= 1) {
        s  += __shfl_xor_sync(0xffffffffu, s,  off);
        ss += __shfl_xor_sync(0xffffffffu, ss, off);
    }
    __shared__ float sh_s[8], sh_ss[8];
    const int w = threadIdx.x >> 5, l = threadIdx.x & 31;
    if (l == 0) { sh_s[w] = s; sh_ss[w] = ss; }
    __syncthreads();
    if (w == 0) {
        s  = (l < 8) ? sh_s[l]  : 0.0f;
        ss = (l < 8) ? sh_ss[l] : 0.0f;
        #pragma unroll
        for (int off = 4; off; off >>= 1) {
            s  += __shfl_xor_sync(0xffffffffu, s,  off);
            ss += __shfl_xor_sync(0xffffffffu, ss, off);
        }
        if (l == 0) { sh_s[0] = s; sh_ss[0] = ss; }
    }
    __syncthreads();
    const float mean = sh_s[0] * (1.0f / D_MODEL);
    const float var  = sh_ss[0] * (1.0f / D_MODEL) - mean * mean;
    const float inv  = rsqrtf(var + 1e-5f);

    const float4 gm = *(const float4*)(gamma + j);
    const float4 bt = *(const float4*)(beta  + j);
    float4 o;
    o.x = (y0 - mean) * inv * gm.x + bt.x;
    o.y = (y1 - mean) * inv * gm.y + bt.y;
    o.z = (y2 - mean) * inv * gm.z + bt.z;
    o.w = (y3 - mean) * inv * gm.w + bt.w;
    *(float4*)(out + (size_t)g * D_MODEL + j) = o;
}

// ---------------- launch ----------------
extern "C" void kernel_launch(void* const* d_in, const int* in_sizes, int n_in,
                              void* d_out, int out_size)
{
    (void)in_sizes; (void)n_in; (void)out_size;
    const float* x     = (const float*)d_in[0];
    const float* A     = (const float*)d_in[1];
    const float* B     = (const float*)d_in[2];
    const float* C     = (const float*)d_in[3];
    const float* Dv    = (const float*)d_in[4];
    const float* W_sel = (const float*)d_in[5];
    const float* b_sel = (const float*)d_in[6];
    const float* gamma = (const float*)d_in[7];
    const float* beta  = (const float*)d_in[8];
    float* out = (float*)d_out;

    float *XA, *SEL, *Y;
    __half *H, *Xh, *Ah, *Bh, *Ch, *Wh;
    cudaGetSymbolAddress((void**)&XA,  g_XA);
    cudaGetSymbolAddress((void**)&SEL, g_SEL);
    cudaGetSymbolAddress((void**)&H,   g_H);
    cudaGetSymbolAddress((void**)&Y,   g_Y);
    cudaGetSymbolAddress((void**)&Xh,  g_Xh);
    cudaGetSymbolAddress((void**)&Ah,  g_Ah);
    cudaGetSymbolAddress((void**)&Bh,  g_Bh);
    cudaGetSymbolAddress((void**)&Ch,  g_Ch);
    cudaGetSymbolAddress((void**)&Wh,  g_Wh);

    cudaFuncSetAttribute(tc_gemm<EPI_NONE>,          cudaFuncAttributeMaxDynamicSharedMemorySize, SMEM_BIG);
    cudaFuncSetAttribute(tc_gemm<EPI_PERM>,          cudaFuncAttributeMaxDynamicSharedMemorySize, SMEM_BIG);
    cudaFuncSetAttribute(tc_gemm<EPI_SIG_BIAS_PERM>, cudaFuncAttributeMaxDynamicSharedMemorySize, SMEM_BIG);
    cudaFuncSetAttribute(rec_kernel,                 cudaFuncAttributeMaxDynamicSharedMemorySize, SMEM_REC);

    // launch 1: x -> fp16
    f2h_kernel<<<(ROWS * D_MODEL / 4) / 256, 256>>>(x, Xh);
    // launch 2: all 4 weight matrices -> fp16 (one kernel)
    f2h_w4_kernel<<<4096, 256>>>(A, Ah, B, Bh, C, Ch, W_sel, Wh);

    const dim3 big_grid(D_MODEL / 128, ROWS / 128);        // 8 x 128

    // launch 3: SEL = sigmoid(x @ Wsel^T + b)  (P-layout fp32)
    tc_gemm<EPI_SIG_BIAS_PERM><<<big_grid, 256, SMEM_BIG>>>(Xh, Wh, SEL, b_sel);
    // launch 4: XA = x @ A^T  (P-layout fp32)
    tc_gemm<EPI_PERM><<<big_grid, 256, SMEM_BIG>>>(Xh, Ah, XA, nullptr);
    // launch 5: full recurrence (h0 + 15 steps), persistent, per-group sync
    rec_kernel<<<128, 256, SMEM_REC>>>(Bh, H, XA, SEL);
    // launch 6: Y = H @ C^T  (P-layout fp32)
    tc_gemm<EPI_NONE><<<big_grid, 256, SMEM_BIG>>>(H, Ch, Y, nullptr);
    // launch 7: LayerNorm + x*D + un-permute
    ln_kernel<<<ROWS, 256>>>(Y, x, Dv, gamma, beta, out);
}